// round 15
// baseline (speedup 1.0000x reference)
#include <cuda_runtime.h>
#include <cuda_fp16.h>
#include <cstdint>
#include <cstddef>

#define kB 64
#define kN 4096
#define kS 8
#define kD 256
#define kM 1024
#define kNITER 3

typedef unsigned long long u64;

// ---------------- f32x2 packed math helpers ----------------
__device__ __forceinline__ u64 pk2(float lo, float hi) {
    u64 r;
    asm("mov.b64 %0, {%1,%2};" : "=l"(r)
        : "r"(__float_as_uint(lo)), "r"(__float_as_uint(hi)));
    return r;
}
__device__ __forceinline__ void upk2(u64 v, float& lo, float& hi) {
    unsigned a, b;
    asm("mov.b64 {%0,%1}, %2;" : "=r"(a), "=r"(b) : "l"(v));
    lo = __uint_as_float(a); hi = __uint_as_float(b);
}
__device__ __forceinline__ u64 fma2_(u64 a, u64 b, u64 c) {
    u64 d;
    asm("fma.rn.f32x2 %0, %1, %2, %3;" : "=l"(d) : "l"(a), "l"(b), "l"(c));
    return d;
}

// ---------------- scratch ----------------
__device__ float g_S0[512 * 256];
__device__ float g_S1[512 * 256];
__device__ float g_qkbuf[512 * 256];
__device__ float g_Ubuf[512 * 256];
__device__ float g_rowsum[512];
__device__ float g_gh[512 * 768];
__device__ float g_Wqk[256 * 256];
__device__ float g_Bcat[256 * 1024];
__device__ float g_c1cat[1024];
__device__ float g_c2cat[1024];
__device__ float g_W1g[1024 * 256];
__device__ float g_c1m[1024];
__device__ float g_c2m[1024];
__device__ float g_Wvih[768 * 256];
__device__ __half g_flnh[(size_t)64 * 4096 * 256];   // LN(features), fp16, 134MB

// ---------------- LN(features) precompute: fp32 -> fp16, once per replay ----------------
__global__ void __launch_bounds__(256) ln_feat_k(
    const float* __restrict__ X, const float* __restrict__ g,
    const float* __restrict__ b, __half* __restrict__ Y)
{
    int w = threadIdx.x >> 5, lane = threadIdx.x & 31;
    size_t row = (size_t)blockIdx.x * 8 + w;
    const float* xp = X + row * 256 + 8 * lane;
    float4 xa = *(const float4*)xp;
    float4 xb = *(const float4*)(xp + 4);
    float s1 = xa.x + xa.y + xa.z + xa.w + xb.x + xb.y + xb.z + xb.w;
    float s2 = xa.x * xa.x + xa.y * xa.y + xa.z * xa.z + xa.w * xa.w
             + xb.x * xb.x + xb.y * xb.y + xb.z * xb.z + xb.w * xb.w;
#pragma unroll
    for (int o = 16; o; o >>= 1) {
        s1 += __shfl_xor_sync(~0u, s1, o);
        s2 += __shfl_xor_sync(~0u, s2, o);
    }
    float mu = s1 * (1.f / 256.f);
    float var = fmaf(-mu, mu, s2 * (1.f / 256.f));
    float rstd = rsqrtf(var + 1e-5f);
    float4 ga = *(const float4*)(g + 8 * lane);
    float4 gb = *(const float4*)(g + 8 * lane + 4);
    float4 ba = *(const float4*)(b + 8 * lane);
    float4 bb = *(const float4*)(b + 8 * lane + 4);
    float o0 = fmaf((xa.x - mu) * rstd, ga.x, ba.x);
    float o1 = fmaf((xa.y - mu) * rstd, ga.y, ba.y);
    float o2 = fmaf((xa.z - mu) * rstd, ga.z, ba.z);
    float o3 = fmaf((xa.w - mu) * rstd, ga.w, ba.w);
    float o4 = fmaf((xb.x - mu) * rstd, gb.x, bb.x);
    float o5 = fmaf((xb.y - mu) * rstd, gb.y, bb.y);
    float o6 = fmaf((xb.z - mu) * rstd, gb.z, bb.z);
    float o7 = fmaf((xb.w - mu) * rstd, gb.w, bb.w);
    __half2 h0 = __floats2half2_rn(o0, o1);
    __half2 h1 = __floats2half2_rn(o2, o3);
    __half2 h2 = __floats2half2_rn(o4, o5);
    __half2 h3 = __floats2half2_rn(o6, o7);
    uint4 pack;
    pack.x = *(unsigned*)&h0; pack.y = *(unsigned*)&h1;
    pack.z = *(unsigned*)&h2; pack.w = *(unsigned*)&h3;
    *(uint4*)(Y + row * 256 + 8 * lane) = pack;
}

// ================= pipelined fp32 GEMM, TMx64x16 tiles =================
template<int DO_LN, int TM>
__global__ void __launch_bounds__(256) gemm2_k(
    const float* __restrict__ A, const float* __restrict__ B,
    float* __restrict__ C, int ldc, float* __restrict__ C2, int ldc2, int splitN,
    int N, int K, int kLen, int bTrans,
    const float* __restrict__ c1, const float* __restrict__ c2, int lnCols,
    const float* __restrict__ rowden, const float* __restrict__ bias,
    int relu, int atomicOut, float* __restrict__ zeroU, float* __restrict__ zeroRS)
{
    constexpr int TK = 16;
    constexpr int RM = TM / 16;
    __shared__ float As[2][TK][TM + 4];
    __shared__ float Bs[2][TK][68];
    __shared__ float smu[TM], srs[TM];
    int tid = threadIdx.x;
    int tx = tid & 15, ty = tid >> 4;
    int m0 = blockIdx.x * TM, n0 = blockIdx.y * 64;
    int kbeg = blockIdx.z * kLen;
    int nk = kLen / TK;
    int ra = tid >> 2, qa = tid & 3;
    int rb = tid >> 4, qb = tid & 15;
    bool aload = (TM == 64) || (tid < TM * 4);

    if (zeroU && blockIdx.y == 0 && blockIdx.z == 0) {
        float4 z4 = make_float4(0.f, 0.f, 0.f, 0.f);
#pragma unroll
        for (int s = 0; s < TM / 4; s++)
            *(float4*)(zeroU + (size_t)m0 * 256 + s * 1024 + tid * 4) = z4;
        if (blockIdx.x == 0 && tid < 128)
            *(float4*)(zeroRS + tid * 4) = z4;
    }

    const float* Aptr = A + (size_t)(m0 + (aload ? ra : 0)) * K + kbeg + 4 * qa;
    const float* BptrT = B + (size_t)(n0 + ra) * K + kbeg + 4 * qa;
    const float* BptrN = B + (size_t)(kbeg + rb) * N + n0 + 4 * qb;

    float s1 = 0.f, s2 = 0.f;
    u64 acc[RM][2];
#pragma unroll
    for (int i = 0; i < RM; i++) { acc[i][0] = 0ull; acc[i][1] = 0ull; }

    float4 va = make_float4(0, 0, 0, 0);
    if (aload) va = *(const float4*)Aptr;
    float4 vb = bTrans ? *(const float4*)BptrT : *(const float4*)BptrN;
    if (aload) {
        As[0][4 * qa + 0][ra] = va.x; As[0][4 * qa + 1][ra] = va.y;
        As[0][4 * qa + 2][ra] = va.z; As[0][4 * qa + 3][ra] = va.w;
    }
    if (DO_LN) {
        s1 += va.x + va.y + va.z + va.w;
        s2 += va.x * va.x + va.y * va.y + va.z * va.z + va.w * va.w;
    }
    if (bTrans) {
        Bs[0][4 * qa + 0][ra] = vb.x; Bs[0][4 * qa + 1][ra] = vb.y;
        Bs[0][4 * qa + 2][ra] = vb.z; Bs[0][4 * qa + 3][ra] = vb.w;
    } else {
        *(float4*)&Bs[0][rb][4 * qb] = vb;
    }
    __syncthreads();

    for (int t = 0; t < nk; t++) {
        int cur = t & 1;
        bool has = (t + 1 < nk);
        if (has) {
            if (aload) va = *(const float4*)(Aptr + (t + 1) * TK);
            vb = bTrans ? *(const float4*)(BptrT + (t + 1) * TK)
                        : *(const float4*)(BptrN + (size_t)(t + 1) * TK * N);
        }
#pragma unroll
        for (int kk = 0; kk < TK; kk++) {
            float4 b4 = *(const float4*)&Bs[cur][kk][tx * 4];
            u64 b0 = pk2(b4.x, b4.y), b1p = pk2(b4.z, b4.w);
            float am[RM];
#pragma unroll
            for (int i = 0; i < RM; i++) am[i] = As[cur][kk][ty * RM + i];
#pragma unroll
            for (int i = 0; i < RM; i++) {
                u64 a2 = pk2(am[i], am[i]);
                acc[i][0] = fma2_(a2, b0, acc[i][0]);
                acc[i][1] = fma2_(a2, b1p, acc[i][1]);
            }
        }
        if (has) {
            int nb = cur ^ 1;
            if (aload) {
                As[nb][4 * qa + 0][ra] = va.x; As[nb][4 * qa + 1][ra] = va.y;
                As[nb][4 * qa + 2][ra] = va.z; As[nb][4 * qa + 3][ra] = va.w;
            }
            if (DO_LN) {
                s1 += va.x + va.y + va.z + va.w;
                s2 += va.x * va.x + va.y * va.y + va.z * va.z + va.w * va.w;
            }
            if (bTrans) {
                Bs[nb][4 * qa + 0][ra] = vb.x; Bs[nb][4 * qa + 1][ra] = vb.y;
                Bs[nb][4 * qa + 2][ra] = vb.z; Bs[nb][4 * qa + 3][ra] = vb.w;
            } else {
                *(float4*)&Bs[nb][rb][4 * qb] = vb;
            }
            __syncthreads();
        }
    }

    if (DO_LN) {
        s1 += __shfl_xor_sync(~0u, s1, 1); s2 += __shfl_xor_sync(~0u, s2, 1);
        s1 += __shfl_xor_sync(~0u, s1, 2); s2 += __shfl_xor_sync(~0u, s2, 2);
        if (aload && (tid & 3) == 0) {
            float mu = s1 * (1.f / 256.f);
            float var = fmaf(-mu, mu, s2 * (1.f / 256.f));
            smu[ra] = mu;
            srs[ra] = rsqrtf(var + 1e-5f);
        }
        __syncthreads();
    }

#pragma unroll
    for (int i = 0; i < RM; i++) {
        int m = m0 + ty * RM + i;
        float c[4];
        upk2(acc[i][0], c[0], c[1]);
        upk2(acc[i][1], c[2], c[3]);
        if (DO_LN) {
            float mu = smu[ty * RM + i], rstd = srs[ty * RM + i];
#pragma unroll
            for (int j = 0; j < 4; j++) {
                int n = n0 + tx * 4 + j;
                float v = c[j];
                if (n < lnCols) v = rstd * (v - mu * c1[n]);
                v += c2[n];
                if (relu) v = fmaxf(v, 0.f);
                if (C2 && n >= splitN) C2[(size_t)m * ldc2 + (n - splitN)] = v;
                else C[(size_t)m * ldc + n] = v;
            }
        } else {
            float rsf = rowden ? __fdividef(1.f, rowden[m]) : 1.f;
#pragma unroll
            for (int j = 0; j < 4; j++) {
                int n = n0 + tx * 4 + j;
                float v = c[j];
                if (rowden) v *= rsf;
                if (bias && blockIdx.z == 0) v += bias[n];
                if (relu) v = fmaxf(v, 0.f);
                if (atomicOut) atomicAdd(&C[(size_t)m * ldc + n], v);
                else C[(size_t)m * ldc + n] = v;
            }
        }
    }
}

// ---------------- C = A^T @ B ----------------
__global__ void __launch_bounds__(256) gemm_tn_k(
    const float* __restrict__ A, const float* __restrict__ Bm, float* __restrict__ C,
    int M, int N, int K)
{
    constexpr int TK = 16;
    __shared__ __align__(16) float As[TK][72];
    __shared__ __align__(16) float Bs[TK][72];
    int tid = threadIdx.x;
    int tx = tid & 15, ty = tid >> 4;
    int m0 = blockIdx.x * 64, n0 = blockIdx.y * 64;

    u64 acc[4][2];
#pragma unroll
    for (int i = 0; i < 4; i++) { acc[i][0] = 0ull; acc[i][1] = 0ull; }

    for (int k0 = 0; k0 < K; k0 += TK) {
        int r = tid >> 4, q = tid & 15;
        *(float4*)&As[r][4 * q] = *(const float4*)(A + (size_t)(k0 + r) * M + m0 + 4 * q);
        *(float4*)&Bs[r][4 * q] = *(const float4*)(Bm + (size_t)(k0 + r) * N + n0 + 4 * q);
        __syncthreads();
#pragma unroll
        for (int kk = 0; kk < TK; kk++) {
            float4 bv = *(const float4*)&Bs[kk][tx * 4];
            u64 b0 = pk2(bv.x, bv.y), b1 = pk2(bv.z, bv.w);
#pragma unroll
            for (int i = 0; i < 4; i++) {
                float a = As[kk][ty * 4 + i];
                u64 a2 = pk2(a, a);
                acc[i][0] = fma2_(a2, b0, acc[i][0]);
                acc[i][1] = fma2_(a2, b1, acc[i][1]);
            }
        }
        __syncthreads();
    }
#pragma unroll
    for (int i = 0; i < 4; i++) {
        int m = m0 + ty * 4 + i;
        float c[4];
        upk2(acc[i][0], c[0], c[1]);
        upk2(acc[i][1], c[2], c[3]);
#pragma unroll
        for (int j = 0; j < 4; j++)
            C[(size_t)m * N + n0 + tx * 4 + j] = c[j];
    }
}

// ---------------- merged precompute builder ----------------
__global__ void __launch_bounds__(256) build_misc_k(
    const float* __restrict__ Wqk, const float* __restrict__ gs,
    const float* __restrict__ bs, const float* __restrict__ whh,
    const float* __restrict__ bhh,
    const float* __restrict__ W1, const float* __restrict__ gm,
    const float* __restrict__ bm, const float* __restrict__ b1,
    float* __restrict__ Bcat, float* __restrict__ c1cat, float* __restrict__ c2cat,
    float* __restrict__ W1g, float* __restrict__ c1m, float* __restrict__ c2m)
{
    int x = blockIdx.x;
    int tid = threadIdx.x;
    if (x < 16) {
        __shared__ float r1[16][17], r2[16][17];
        int nn = tid & 15, kg = tid >> 4;
        int n = 16 * x + nn;
        float lc1 = 0.f, lc2 = 0.f;
#pragma unroll
        for (int r = 0; r < 16; r++) {
            int k = kg * 16 + r;
            float w = Wqk[(size_t)k * 256 + n];
            float gw = gs[k] * w;
            Bcat[(size_t)k * 1024 + n] = gw;
            lc1 += gw;
            lc2 += bs[k] * w;
        }
        r1[kg][nn] = lc1; r2[kg][nn] = lc2;
        __syncthreads();
        if (kg == 0) {
            float a = 0.f, b = 0.f;
#pragma unroll
            for (int i = 0; i < 16; i++) { a += r1[i][nn]; b += r2[i][nn]; }
            c1cat[n] = a; c2cat[n] = b;
        }
    } else if (x < 208) {
        __shared__ float tile[32][33];
        int t = x - 16;
        int n0 = (t % 24) * 32, k0 = (t / 24) * 32;
        int tx = tid & 31, ty = tid >> 5;
#pragma unroll
        for (int i = 0; i < 4; i++)
            tile[ty + 8 * i][tx] = whh[(size_t)(n0 + ty + 8 * i) * 256 + k0 + tx];
        __syncthreads();
#pragma unroll
        for (int i = 0; i < 4; i++)
            Bcat[(size_t)(k0 + ty + 8 * i) * 1024 + 256 + n0 + tx] = tile[tx][ty + 8 * i];
    } else if (x < 211) {
        int i = (x - 208) * 256 + tid;
        if (i < 768) c2cat[256 + i] = bhh[i];
    } else {
        int w = tid >> 5, lane = tid & 31;
        int row = (x - 211) * 8 + w;
        float lc1 = 0.f, lc2 = 0.f;
#pragma unroll
        for (int j = 0; j < 8; j++) {
            int col = lane + 32 * j;
            float v = W1[(size_t)row * 256 + col];
            float sc = gm[col] * v;
            W1g[(size_t)row * 256 + col] = sc;
            lc1 += sc;
            lc2 += bm[col] * v;
        }
#pragma unroll
        for (int o = 16; o; o >>= 1) {
            lc1 += __shfl_xor_sync(~0u, lc1, o);
            lc2 += __shfl_xor_sync(~0u, lc2, o);
        }
        if (lane == 0) { c1m[row] = lc1; c2m[row] = lc2 + b1[row]; }
    }
}

// ---------------- fused attention: warp-private rows, zero smem phases ----------------
// Block = 256 rows of batch b, 8 tiles of 32; warp owns 4 rows/tile for ALL 8 slots.
// Lane owns cols p0:(4l,4l+1) p1:(4l+2,4l+3) p2:(128+4l,..) p3:(128+4l+2,..).
// Merge tree lands dot d[slot=lane&7]; softmax distributed over 8-lane groups.
__global__ void __launch_bounds__(256) attn_fused_k(
    const __half* __restrict__ flnh, const float* __restrict__ qk,
    float* __restrict__ attn_out, float* __restrict__ U, float* __restrict__ rowsum)
{
    __shared__ float Us[8 * 264];
    int tid = threadIdx.x, lane = tid & 31, w = tid >> 5;
    int b = blockIdx.y;
    int n0 = blockIdx.x * 256;

    // qk for all 8 slots in registers
    u64 qk2[8][4];
#pragma unroll
    for (int s = 0; s < 8; s++) {
        const float* qp = qk + ((size_t)(b * 8 + s) << 8) + 4 * lane;
        float4 qa_ = *(const float4*)qp;
        float4 qb_ = *(const float4*)(qp + 128);
        qk2[s][0] = pk2(qa_.x, qa_.y); qk2[s][1] = pk2(qa_.z, qa_.w);
        qk2[s][2] = pk2(qb_.x, qb_.y); qk2[s][3] = pk2(qb_.z, qb_.w);
    }

    u64 u2[8][4];
#pragma unroll
    for (int s = 0; s < 8; s++)
#pragma unroll
        for (int p = 0; p < 4; p++) u2[s][p] = 0ull;
    float rs_acc = 0.f;   // slot (lane&7), replicated x4

    for (int t = 0; t < 8; t++) {
        const __half* fp = flnh + ((size_t)b * kN + n0 + t * 32 + 4 * w) * 256 + 4 * lane;
        // load 4 rows into registers (batched LDGs)
        u64 x2[4][4];
#pragma unroll
        for (int r = 0; r < 4; r++) {
            uint2 ha = *(const uint2*)(fp + (size_t)r * 256);
            uint2 hb = *(const uint2*)(fp + (size_t)r * 256 + 128);
            float2 f0 = __half22float2(*(__half2*)&ha.x);
            float2 f1 = __half22float2(*(__half2*)&ha.y);
            float2 f2c = __half22float2(*(__half2*)&hb.x);
            float2 f3 = __half22float2(*(__half2*)&hb.y);
            x2[r][0] = pk2(f0.x, f0.y); x2[r][1] = pk2(f1.x, f1.y);
            x2[r][2] = pk2(f2c.x, f2c.y); x2[r][3] = pk2(f3.x, f3.y);
        }
        float aout = 0.f;
#pragma unroll
        for (int r = 0; r < 4; r++) {
            // 8 dots
            float d[8];
#pragma unroll
            for (int s = 0; s < 8; s++) {
                u64 acc = 0ull;
#pragma unroll
                for (int p = 0; p < 4; p++) acc = fma2_(qk2[s][p], x2[r][p], acc);
                float lo, hi; upk2(acc, lo, hi);
                d[s] = lo + hi;
            }
            // merge tree: 16 shfl + 7 sel -> dd = dot[lane&7] over all 32 lanes
            d[0] += __shfl_xor_sync(~0u, d[0], 1);
            d[1] += __shfl_xor_sync(~0u, d[1], 1);
            d[2] += __shfl_xor_sync(~0u, d[2], 1);
            d[3] += __shfl_xor_sync(~0u, d[3], 1);
            d[4] += __shfl_xor_sync(~0u, d[4], 1);
            d[5] += __shfl_xor_sync(~0u, d[5], 1);
            d[6] += __shfl_xor_sync(~0u, d[6], 1);
            d[7] += __shfl_xor_sync(~0u, d[7], 1);
            float m01 = (lane & 1) ? d[1] : d[0];
            float m23 = (lane & 1) ? d[3] : d[2];
            float m45 = (lane & 1) ? d[5] : d[4];
            float m67 = (lane & 1) ? d[7] : d[6];
            m01 += __shfl_xor_sync(~0u, m01, 2);
            m23 += __shfl_xor_sync(~0u, m23, 2);
            m45 += __shfl_xor_sync(~0u, m45, 2);
            m67 += __shfl_xor_sync(~0u, m67, 2);
            float q03 = (lane & 2) ? m23 : m01;
            float q47 = (lane & 2) ? m67 : m45;
            q03 += __shfl_xor_sync(~0u, q03, 4);
            q47 += __shfl_xor_sync(~0u, q47, 4);
            float dd = (lane & 4) ? q47 : q03;
            dd += __shfl_xor_sync(~0u, dd, 8);
            dd += __shfl_xor_sync(~0u, dd, 16);
            // distributed softmax over 8-lane group (slots)
            float mx = dd;
            mx = fmaxf(mx, __shfl_xor_sync(~0u, mx, 1));
            mx = fmaxf(mx, __shfl_xor_sync(~0u, mx, 2));
            mx = fmaxf(mx, __shfl_xor_sync(~0u, mx, 4));
            float e = __expf(0.0625f * (dd - mx));
            float sum = e;
            sum += __shfl_xor_sync(~0u, sum, 1);
            sum += __shfl_xor_sync(~0u, sum, 2);
            sum += __shfl_xor_sync(~0u, sum, 4);
            float a = fmaf(e, __fdividef(1.f, sum), 1e-8f);
            rs_acc += a;
            if ((lane >> 3) == r) aout = a;
            // U accumulate: broadcast a[slot s] from lane s
#pragma unroll
            for (int s = 0; s < 8; s++) {
                float as = __shfl_sync(~0u, a, s);
                u64 a2 = pk2(as, as);
#pragma unroll
                for (int p = 0; p < 4; p++) u2[s][p] = fma2_(a2, x2[r][p], u2[s][p]);
            }
        }
        // coalesced-sectored attn store: lane -> (row lane>>3, slot lane&7)
        int gr = n0 + t * 32 + 4 * w + (lane >> 3);
        attn_out[(size_t)(b * 8 + (lane & 7)) * 4096 + gr] = aout;
    }

    // ---- block U reduction ----
#pragma unroll
    for (int i = 0; i < 8; i++) Us[i * 264 + tid] = 0.f;
    __syncthreads();
#pragma unroll
    for (int s = 0; s < 8; s++)
#pragma unroll
        for (int p = 0; p < 4; p++) {
            float lo, hi; upk2(u2[s][p], lo, hi);
            int base = (p < 2) ? (4 * lane + 2 * p) : (128 + 4 * lane + 2 * (p - 2));
            atomicAdd(&Us[s * 264 + base], lo);
            atomicAdd(&Us[s * 264 + base + 1], hi);
        }
    __syncthreads();
#pragma unroll
    for (int i = 0; i < 8; i++)
        atomicAdd(&U[((size_t)(b * 8 + i) << 8) + tid], Us[i * 264 + tid]);
    // rowsum: rs_acc replicated on lanes s, s+8, s+16, s+24; lanes 0..7 commit
    if (lane < 8)
        atomicAdd(&rowsum[b * 8 + lane], rs_acc);
}

// ---------------- fused gi-GEMM (3 gates) + GRU, TM=32 ----------------
__global__ void __launch_bounds__(256) gru_gemm_k(
    const float* __restrict__ Uin, const float* __restrict__ Wvih,
    const float* __restrict__ rowsum, const float* __restrict__ b_ih,
    const float* __restrict__ gh, float* __restrict__ S0, float* __restrict__ S1)
{
    constexpr int TK = 16;
    __shared__ float As[2][TK][36];
    __shared__ float Bs[2][TK][208];
    int tid = threadIdx.x;
    int tx = tid & 15, ty = tid >> 4;
    int m0 = blockIdx.x * 32, c0 = blockIdx.y * 64;
    int ra = tid >> 2, qa = tid & 3;
    bool aload = tid < 128;

    const float* Aptr = Uin + (size_t)(m0 + (ra & 31)) * 256 + 4 * qa;

    u64 acc[3][2][2];
#pragma unroll
    for (int g = 0; g < 3; g++)
#pragma unroll
        for (int i = 0; i < 2; i++) { acc[g][i][0] = 0ull; acc[g][i][1] = 0ull; }

    float4 va = aload ? *(const float4*)Aptr : make_float4(0, 0, 0, 0);
    float4 vb[3];
#pragma unroll
    for (int g = 0; g < 3; g++)
        vb[g] = *(const float4*)(Wvih + (size_t)(g * 256 + c0 + ra) * 256 + 4 * qa);
    if (aload) {
        As[0][4 * qa + 0][ra] = va.x; As[0][4 * qa + 1][ra] = va.y;
        As[0][4 * qa + 2][ra] = va.z; As[0][4 * qa + 3][ra] = va.w;
    }
#pragma unroll
    for (int g = 0; g < 3; g++) {
        Bs[0][4 * qa + 0][g * 64 + ra] = vb[g].x;
        Bs[0][4 * qa + 1][g * 64 + ra] = vb[g].y;
        Bs[0][4 * qa + 2][g * 64 + ra] = vb[g].z;
        Bs[0][4 * qa + 3][g * 64 + ra] = vb[g].w;
    }
    __syncthreads();

    for (int t = 0; t < 16; t++) {
        int cur = t & 1;
        bool has = (t + 1 < 16);
        if (has) {
            if (aload) va = *(const float4*)(Aptr + (t + 1) * TK);
#pragma unroll
            for (int g = 0; g < 3; g++)
                vb[g] = *(const float4*)(Wvih + (size_t)(g * 256 + c0 + ra) * 256
                                         + (t + 1) * TK + 4 * qa);
        }
#pragma unroll
        for (int kk = 0; kk < TK; kk++) {
            float2 a2f = *(const float2*)&As[cur][kk][ty * 2];
            float am[2] = {a2f.x, a2f.y};
#pragma unroll
            for (int g = 0; g < 3; g++) {
                float4 b4 = *(const float4*)&Bs[cur][kk][g * 64 + tx * 4];
                u64 b0 = pk2(b4.x, b4.y), b1p = pk2(b4.z, b4.w);
#pragma unroll
                for (int i = 0; i < 2; i++) {
                    u64 a2 = pk2(am[i], am[i]);
                    acc[g][i][0] = fma2_(a2, b0, acc[g][i][0]);
                    acc[g][i][1] = fma2_(a2, b1p, acc[g][i][1]);
                }
            }
        }
        if (has) {
            int nb = cur ^ 1;
            if (aload) {
                As[nb][4 * qa + 0][ra] = va.x; As[nb][4 * qa + 1][ra] = va.y;
                As[nb][4 * qa + 2][ra] = va.z; As[nb][4 * qa + 3][ra] = va.w;
            }
#pragma unroll
            for (int g = 0; g < 3; g++) {
                Bs[nb][4 * qa + 0][g * 64 + ra] = vb[g].x;
                Bs[nb][4 * qa + 1][g * 64 + ra] = vb[g].y;
                Bs[nb][4 * qa + 2][g * 64 + ra] = vb[g].z;
                Bs[nb][4 * qa + 3][g * 64 + ra] = vb[g].w;
            }
            __syncthreads();
        }
    }

#pragma unroll
    for (int i = 0; i < 2; i++) {
        int m = m0 + ty * 2 + i;
        float inv = __fdividef(1.f, rowsum[m]);
        float rg_[4], zg[4], ng[4];
        upk2(acc[0][i][0], rg_[0], rg_[1]); upk2(acc[0][i][1], rg_[2], rg_[3]);
        upk2(acc[1][i][0], zg[0], zg[1]);   upk2(acc[1][i][1], zg[2], zg[3]);
        upk2(acc[2][i][0], ng[0], ng[1]);   upk2(acc[2][i][1], ng[2], ng[3]);
#pragma unroll
        for (int j = 0; j < 4; j++) {
            int c = c0 + tx * 4 + j;
            float ir = fmaf(rg_[j], inv, b_ih[c]);
            float iz = fmaf(zg[j], inv, b_ih[256 + c]);
            float in_ = fmaf(ng[j], inv, b_ih[512 + c]);
            size_t gb = (size_t)m * 768 + c;
            float hr = gh[gb], hz = gh[gb + 256], hn = gh[gb + 512];
            float r = 1.f / (1.f + __expf(-(ir + hr)));
            float z = 1.f / (1.f + __expf(-(iz + hz)));
            float nv = tanhf(fmaf(r, hn, in_));
            float h = S1[(size_t)m * 256 + c];
            float v = fmaf(z, h - nv, nv);
            S0[(size_t)m * 256 + c] = v;
            S1[(size_t)m * 256 + c] = v;
        }
    }
}

// ---------------- fused MLP, TM=64 ----------------
__global__ void __launch_bounds__(256) mlp_k(
    const float* __restrict__ S0, const float* __restrict__ W1g,
    const float* __restrict__ c1, const float* __restrict__ c2,
    const float* __restrict__ W2, const float* __restrict__ b2,
    float* __restrict__ S1)
{
    constexpr int TK = 16;
    __shared__ __align__(16) float sbuf[4352];
    __shared__ float hs[64][68];
    __shared__ float smu[64], srs[64];
#define AS_(b,k,i) sbuf[(b) * 1088 + (k) * 68 + (i)]
#define BS_(b,k,i) sbuf[2176 + (b) * 1088 + (k) * 68 + (i)]
#define W2S_(k,o)  sbuf[(k) * 68 + (o)]
    int tid = threadIdx.x;
    int tx = tid & 15, ty = tid >> 4;
    int m0 = blockIdx.x * 64, h0 = blockIdx.y * 64;
    int ra = tid >> 2, qa = tid & 3;

    const float* Aptr = S0 + (size_t)(m0 + ra) * 256 + 4 * qa;
    const float* Bptr = W1g + (size_t)(h0 + ra) * 256 + 4 * qa;

    float s1 = 0.f, s2 = 0.f;
    u64 acc[4][2];
#pragma unroll
    for (int i = 0; i < 4; i++) { acc[i][0] = 0ull; acc[i][1] = 0ull; }

    float4 va = *(const float4*)Aptr;
    float4 vb = *(const float4*)Bptr;
    AS_(0, 4 * qa + 0, ra) = va.x; AS_(0, 4 * qa + 1, ra) = va.y;
    AS_(0, 4 * qa + 2, ra) = va.z; AS_(0, 4 * qa + 3, ra) = va.w;
    s1 += va.x + va.y + va.z + va.w;
    s2 += va.x * va.x + va.y * va.y + va.z * va.z + va.w * va.w;
    BS_(0, 4 * qa + 0, ra) = vb.x; BS_(0, 4 * qa + 1, ra) = vb.y;
    BS_(0, 4 * qa + 2, ra) = vb.z; BS_(0, 4 * qa + 3, ra) = vb.w;
    __syncthreads();

    for (int t = 0; t < 16; t++) {
        int cur = t & 1;
        bool has = (t + 1 < 16);
        if (has) {
            va = *(const float4*)(Aptr + (t + 1) * TK);
            vb = *(const float4*)(Bptr + (t + 1) * TK);
        }
#pragma unroll
        for (int kk = 0; kk < TK; kk++) {
            float4 a4 = *(const float4*)&AS_(cur, kk, ty * 4);
            float4 b4 = *(const float4*)&BS_(cur, kk, tx * 4);
            u64 b0 = pk2(b4.x, b4.y), b1p = pk2(b4.z, b4.w);
            float am[4] = {a4.x, a4.y, a4.z, a4.w};
#pragma unroll
            for (int i = 0; i < 4; i++) {
                u64 a2 = pk2(am[i], am[i]);
                acc[i][0] = fma2_(a2, b0, acc[i][0]);
                acc[i][1] = fma2_(a2, b1p, acc[i][1]);
            }
        }
        if (has) {
            int nb = cur ^ 1;
            AS_(nb, 4 * qa + 0, ra) = va.x; AS_(nb, 4 * qa + 1, ra) = va.y;
            AS_(nb, 4 * qa + 2, ra) = va.z; AS_(nb, 4 * qa + 3, ra) = va.w;
            s1 += va.x + va.y + va.z + va.w;
            s2 += va.x * va.x + va.y * va.y + va.z * va.z + va.w * va.w;
            BS_(nb, 4 * qa + 0, ra) = vb.x; BS_(nb, 4 * qa + 1, ra) = vb.y;
            BS_(nb, 4 * qa + 2, ra) = vb.z; BS_(nb, 4 * qa + 3, ra) = vb.w;
            __syncthreads();
        }
    }

    s1 += __shfl_xor_sync(~0u, s1, 1); s2 += __shfl_xor_sync(~0u, s2, 1);
    s1 += __shfl_xor_sync(~0u, s1, 2); s2 += __shfl_xor_sync(~0u, s2, 2);
    if ((tid & 3) == 0) {
        float mu = s1 * (1.f / 256.f);
        float var = fmaf(-mu, mu, s2 * (1.f / 256.f));
        smu[ra] = mu;
        srs[ra] = rsqrtf(var + 1e-5f);
    }
    __syncthreads();

#pragma unroll
    for (int i = 0; i < 4; i++) {
        float mu = smu[ty * 4 + i], rstd = srs[ty * 4 + i];
        float c[4];
        upk2(acc[i][0], c[0], c[1]);
        upk2(acc[i][1], c[2], c[3]);
#pragma unroll
        for (int j = 0; j < 4; j++) {
            int n = h0 + tx * 4 + j;
            float v = rstd * (c[j] - mu * c1[n]) + c2[n];
            hs[ty * 4 + i][tx * 4 + j] = fmaxf(v, 0.f);
        }
    }
    __syncthreads();

    for (int ot = 0; ot < 4; ot++) {
#pragma unroll
        for (int tq = 0; tq < 4; tq++) {
            float4 w4 = *(const float4*)(W2 + (size_t)(ot * 64 + ra) * 1024 + h0
                                         + 16 * qa + 4 * tq);
            W2S_(16 * qa + 4 * tq + 0, ra) = w4.x;
            W2S_(16 * qa + 4 * tq + 1, ra) = w4.y;
            W2S_(16 * qa + 4 * tq + 2, ra) = w4.z;
            W2S_(16 * qa + 4 * tq + 3, ra) = w4.w;
        }
        __syncthreads();

        u64 acc2[4][2];
#pragma unroll
        for (int i = 0; i < 4; i++) { acc2[i][0] = 0ull; acc2[i][1] = 0ull; }
#pragma unroll
        for (int k4 = 0; k4 < 64; k4 += 4) {
            float4 h4[4];
#pragma unroll
            for (int i = 0; i < 4; i++)
                h4[i] = *(const float4*)&hs[ty * 4 + i][k4];
#pragma unroll
            for (int u = 0; u < 4; u++) {
                float4 b4 = *(const float4*)&W2S_(k4 + u, tx * 4);
                u64 b0 = pk2(b4.x, b4.y), b1p = pk2(b4.z, b4.w);
                float hm[4] = {
                    u == 0 ? h4[0].x : u == 1 ? h4[0].y : u == 2 ? h4[0].z : h4[0].w,
                    u == 0 ? h4[1].x : u == 1 ? h4[1].y : u == 2 ? h4[1].z : h4[1].w,
                    u == 0 ? h4[2].x : u == 1 ? h4[2].y : u == 2 ? h4[2].z : h4[2].w,
                    u == 0 ? h4[3].x : u == 1 ? h4[3].y : u == 2 ? h4[3].z : h4[3].w};
#pragma unroll
                for (int i = 0; i < 4; i++) {
                    u64 a2 = pk2(hm[i], hm[i]);
                    acc2[i][0] = fma2_(a2, b0, acc2[i][0]);
                    acc2[i][1] = fma2_(a2, b1p, acc2[i][1]);
                }
            }
        }
#pragma unroll
        for (int i = 0; i < 4; i++) {
            int m = m0 + ty * 4 + i;
            float c[4];
            upk2(acc2[i][0], c[0], c[1]);
            upk2(acc2[i][1], c[2], c[3]);
#pragma unroll
            for (int j = 0; j < 4; j++) {
                int n = ot * 64 + tx * 4 + j;
                float v = c[j];
                if (blockIdx.y == 0) v += b2[n];
                atomicAdd(&S1[(size_t)m * 256 + n], v);
            }
        }
        __syncthreads();
    }
#undef AS_
#undef BS_
#undef W2S_
}

// ---------------- launcher ----------------
extern "C" void kernel_launch(void* const* d_in, const int* in_sizes, int n_in,
                              void* d_out, int out_size)
{
    const float* features   = (const float*)d_in[0];
    const float* slots_init = (const float*)d_in[1];
    const float* g_feat     = (const float*)d_in[2];
    const float* b_feat     = (const float*)d_in[3];
    const float* g_slots    = (const float*)d_in[4];
    const float* b_slots    = (const float*)d_in[5];
    const float* g_mlp      = (const float*)d_in[6];
    const float* b_mlp      = (const float*)d_in[7];
    const float* Wk         = (const float*)d_in[8];
    const float* Wv         = (const float*)d_in[9];
    const float* Wq         = (const float*)d_in[10];
    const float* w_ih       = (const float*)d_in[11];
    const float* w_hh       = (const float*)d_in[12];
    const float* b_ih       = (const float*)d_in[13];
    const float* b_hh       = (const float*)d_in[14];
    const float* W1         = (const float*)d_in[15];
    const float* b1         = (const float*)d_in[16];
    const float* W2         = (const float*)d_in[17];
    const float* b2         = (const float*)d_in[18];

    float* out       = (float*)d_out;
    float* out_slots = out;
    float* out_attn  = out + (size_t)64 * 8 * 256;

    float *S0, *S1, *qkbuf, *U, *rowsum, *gh;
    float *Wqk, *Bcat, *c1cat, *c2cat, *W1g, *c1m, *c2m, *Wvih;
    __half* flnh;
    cudaGetSymbolAddress((void**)&S0, g_S0);
    cudaGetSymbolAddress((void**)&S1, g_S1);
    cudaGetSymbolAddress((void**)&qkbuf, g_qkbuf);
    cudaGetSymbolAddress((void**)&U, g_Ubuf);
    cudaGetSymbolAddress((void**)&rowsum, g_rowsum);
    cudaGetSymbolAddress((void**)&gh, g_gh);
    cudaGetSymbolAddress((void**)&Wqk, g_Wqk);
    cudaGetSymbolAddress((void**)&Bcat, g_Bcat);
    cudaGetSymbolAddress((void**)&c1cat, g_c1cat);
    cudaGetSymbolAddress((void**)&c2cat, g_c2cat);
    cudaGetSymbolAddress((void**)&W1g, g_W1g);
    cudaGetSymbolAddress((void**)&c1m, g_c1m);
    cudaGetSymbolAddress((void**)&c2m, g_c2m);
    cudaGetSymbolAddress((void**)&Wvih, g_Wvih);
    cudaGetSymbolAddress((void**)&flnh, g_flnh);

    // LN(features) -> fp16, once per replay (iteration-invariant)
    ln_feat_k<<<64 * 4096 / 8, 256>>>(features, g_feat, b_feat, flnh);

    gemm_tn_k<<<dim3(4, 4), 256>>>(Wq, Wk, Wqk, 256, 256, 256);
    build_misc_k<<<339, 256>>>(Wqk, g_slots, b_slots, w_hh, b_hh,
                               W1, g_mlp, b_mlp, b1,
                               Bcat, c1cat, c2cat, W1g, c1m, c2m);
    gemm2_k<0, 64><<<dim3(12, 4), 256>>>(w_ih, Wv, Wvih, 256, nullptr, 0, 1 << 30,
                                         256, 256, 256, 0,
                                         nullptr, nullptr, 0, nullptr, nullptr, 0, 0,
                                         nullptr, nullptr);

    cudaMemcpyAsync(S1, slots_init, (size_t)512 * 256 * 4,
                    cudaMemcpyDeviceToDevice, 0);

    for (int it = 0; it < kNITER; it++) {
        // [qk | gh] = LN(S1)@Wqk | S1@w_hh^T + b_hh; side job: zero U/rowsum
        gemm2_k<1, 32><<<dim3(16, 16), 256>>>(S1, Bcat, qkbuf, 256, gh, 768, 256,
                                              1024, 256, 256, 0,
                                              c1cat, c2cat, 256, nullptr, nullptr, 0, 0,
                                              U, rowsum);
        attn_fused_k<<<dim3(16, 64), 256>>>(flnh, qkbuf, out_attn, U, rowsum);
        gru_gemm_k<<<dim3(16, 4), 256>>>(U, Wvih, rowsum, b_ih, gh, S0, S1);
        mlp_k<<<dim3(8, 16), 256>>>(S0, W1g, c1m, c2m, W2, b2, S1);
    }
    cudaMemcpyAsync(out_slots, S1, (size_t)512 * 256 * 4,
                    cudaMemcpyDeviceToDevice, 0);
}

// round 17
// speedup vs baseline: 1.2901x; 1.2901x over previous
#include <cuda_runtime.h>
#include <cuda_fp16.h>
#include <cstdint>
#include <cstddef>

#define kB 64
#define kN 4096
#define kS 8
#define kD 256
#define kM 1024
#define kNITER 3

typedef unsigned long long u64;

// ---------------- f32x2 packed math helpers ----------------
__device__ __forceinline__ u64 pk2(float lo, float hi) {
    u64 r;
    asm("mov.b64 %0, {%1,%2};" : "=l"(r)
        : "r"(__float_as_uint(lo)), "r"(__float_as_uint(hi)));
    return r;
}
__device__ __forceinline__ void upk2(u64 v, float& lo, float& hi) {
    unsigned a, b;
    asm("mov.b64 {%0,%1}, %2;" : "=r"(a), "=r"(b) : "l"(v));
    lo = __uint_as_float(a); hi = __uint_as_float(b);
}
__device__ __forceinline__ u64 fma2_(u64 a, u64 b, u64 c) {
    u64 d;
    asm("fma.rn.f32x2 %0, %1, %2, %3;" : "=l"(d) : "l"(a), "l"(b), "l"(c));
    return d;
}

// ---------------- scratch ----------------
__device__ float g_S0[512 * 256];
__device__ float g_S1[512 * 256];
__device__ float g_qkbuf[512 * 256];
__device__ float g_Ubuf[512 * 256];
__device__ float g_rowsum[512];
__device__ float g_gh[512 * 768];
__device__ float g_Wqk[256 * 256];
__device__ float g_Bcat[256 * 1024];
__device__ float g_c1cat[1024];
__device__ float g_c2cat[1024];
__device__ float g_W1g[1024 * 256];
__device__ float g_c1m[1024];
__device__ float g_c2m[1024];
__device__ float g_Wvih[768 * 256];
__device__ __half g_flnh[(size_t)64 * 4096 * 256];   // LN(features), fp16, 134MB

// ================= mega precompute: [gemm_tn | Wvih gemm | S1 copy | ln_feat] =================
// x in [0,16):    Wqk = Wq^T @ Wk            (64x64 tile; bx=x&3 (m), by=x>>2 (n))
// x in [16,64):   Wvih = w_ih @ Wv           (64x64 tile; t=x-16: m0=(t%12)*64, n0=(t/12)*64)
// x in [64,192):  S1 = slots_init            (float4 copy)
// x >= 192:       ln_feat row block (8 rows) (fp32 -> fp16 LN(features))
// GEMM/copy blocks are FIRST so wave 1 runs them concurrently with ln_feat.
__global__ void __launch_bounds__(256) mega_pre_k(
    const float* __restrict__ features, const float* __restrict__ gf,
    const float* __restrict__ bf, __half* __restrict__ Y,
    const float* __restrict__ Wq, const float* __restrict__ Wk,
    float* __restrict__ Wqk,
    const float* __restrict__ w_ih, const float* __restrict__ Wv,
    float* __restrict__ Wvih,
    const float* __restrict__ slots_init, float* __restrict__ S1)
{
    __shared__ __align__(16) float As[16][72];
    __shared__ __align__(16) float Bs[16][72];
    int x = blockIdx.x;
    int tid = threadIdx.x;

    if (x < 64) {
        // ---- tiled 64x64 GEMM (two variants) ----
        int tx = tid & 15, ty = tid >> 4;
        u64 acc[4][2];
#pragma unroll
        for (int i = 0; i < 4; i++) { acc[i][0] = 0ull; acc[i][1] = 0ull; }
        int m0, n0;
        bool tn = (x < 16);
        if (tn) { m0 = (x & 3) * 64; n0 = (x >> 2) * 64; }
        else { int t = x - 16; m0 = (t % 12) * 64; n0 = (t / 12) * 64; }
        int ra = tid >> 2, qa = tid & 3;
        int rb = tid >> 4, qb = tid & 15;

        for (int k0 = 0; k0 < 256; k0 += 16) {
            if (tn) {
                // A^T: As[k][m] from Wq[(k0+r)*256 + m0+4q]; Bs[k][n] from Wk
                *(float4*)&As[rb][4 * qb] =
                    *(const float4*)(Wq + (size_t)(k0 + rb) * 256 + m0 + 4 * qb);
                *(float4*)&Bs[rb][4 * qb] =
                    *(const float4*)(Wk + (size_t)(k0 + rb) * 256 + n0 + 4 * qb);
            } else {
                // A row-major: transpose-store; B [K,N] direct
                float4 va = *(const float4*)(w_ih + (size_t)(m0 + ra) * 256 + k0 + 4 * qa);
                As[4 * qa + 0][ra] = va.x; As[4 * qa + 1][ra] = va.y;
                As[4 * qa + 2][ra] = va.z; As[4 * qa + 3][ra] = va.w;
                *(float4*)&Bs[rb][4 * qb] =
                    *(const float4*)(Wv + (size_t)(k0 + rb) * 256 + n0 + 4 * qb);
            }
            __syncthreads();
#pragma unroll
            for (int kk = 0; kk < 16; kk++) {
                float4 bv = *(const float4*)&Bs[kk][tx * 4];
                u64 b0 = pk2(bv.x, bv.y), b1 = pk2(bv.z, bv.w);
#pragma unroll
                for (int i = 0; i < 4; i++) {
                    float a = As[kk][ty * 4 + i];
                    u64 a2 = pk2(a, a);
                    acc[i][0] = fma2_(a2, b0, acc[i][0]);
                    acc[i][1] = fma2_(a2, b1, acc[i][1]);
                }
            }
            __syncthreads();
        }
        float* C = tn ? Wqk : Wvih;
#pragma unroll
        for (int i = 0; i < 4; i++) {
            int m = m0 + ty * 4 + i;
            float c[4];
            upk2(acc[i][0], c[0], c[1]);
            upk2(acc[i][1], c[2], c[3]);
#pragma unroll
            for (int j = 0; j < 4; j++)
                C[(size_t)m * 256 + n0 + tx * 4 + j] = c[j];
        }
    } else if (x < 192) {
        int i = (x - 64) * 1024 + tid * 4;
        *(float4*)(S1 + i) = *(const float4*)(slots_init + i);
    } else {
        // ---- ln_feat: one row of 256 per warp ----
        int w = tid >> 5, lane = tid & 31;
        size_t row = (size_t)(x - 192) * 8 + w;
        const float* xp = features + row * 256 + 8 * lane;
        float4 xa = *(const float4*)xp;
        float4 xb = *(const float4*)(xp + 4);
        float s1 = xa.x + xa.y + xa.z + xa.w + xb.x + xb.y + xb.z + xb.w;
        float s2 = xa.x * xa.x + xa.y * xa.y + xa.z * xa.z + xa.w * xa.w
                 + xb.x * xb.x + xb.y * xb.y + xb.z * xb.z + xb.w * xb.w;
#pragma unroll
        for (int o = 16; o; o >>= 1) {
            s1 += __shfl_xor_sync(~0u, s1, o);
            s2 += __shfl_xor_sync(~0u, s2, o);
        }
        float mu = s1 * (1.f / 256.f);
        float var = fmaf(-mu, mu, s2 * (1.f / 256.f));
        float rstd = rsqrtf(var + 1e-5f);
        float4 ga = *(const float4*)(gf + 8 * lane);
        float4 gb = *(const float4*)(gf + 8 * lane + 4);
        float4 ba = *(const float4*)(bf + 8 * lane);
        float4 bb = *(const float4*)(bf + 8 * lane + 4);
        float o0 = fmaf((xa.x - mu) * rstd, ga.x, ba.x);
        float o1 = fmaf((xa.y - mu) * rstd, ga.y, ba.y);
        float o2 = fmaf((xa.z - mu) * rstd, ga.z, ba.z);
        float o3 = fmaf((xa.w - mu) * rstd, ga.w, ba.w);
        float o4 = fmaf((xb.x - mu) * rstd, gb.x, bb.x);
        float o5 = fmaf((xb.y - mu) * rstd, gb.y, bb.y);
        float o6 = fmaf((xb.z - mu) * rstd, gb.z, bb.z);
        float o7 = fmaf((xb.w - mu) * rstd, gb.w, bb.w);
        __half2 h0 = __floats2half2_rn(o0, o1);
        __half2 h1 = __floats2half2_rn(o2, o3);
        __half2 h2 = __floats2half2_rn(o4, o5);
        __half2 h3 = __floats2half2_rn(o6, o7);
        uint4 pack;
        pack.x = *(unsigned*)&h0; pack.y = *(unsigned*)&h1;
        pack.z = *(unsigned*)&h2; pack.w = *(unsigned*)&h3;
        *(uint4*)(Y + row * 256 + 8 * lane) = pack;
    }
}

// ================= pipelined fp32 GEMM, TMx64x16 tiles =================
template<int DO_LN, int TM>
__global__ void __launch_bounds__(256) gemm2_k(
    const float* __restrict__ A, const float* __restrict__ B,
    float* __restrict__ C, int ldc, float* __restrict__ C2, int ldc2, int splitN,
    int N, int K, int kLen, int bTrans,
    const float* __restrict__ c1, const float* __restrict__ c2, int lnCols,
    const float* __restrict__ rowden, const float* __restrict__ bias,
    int relu, int atomicOut, float* __restrict__ zeroU, float* __restrict__ zeroRS)
{
    constexpr int TK = 16;
    constexpr int RM = TM / 16;
    __shared__ float As[2][TK][TM + 4];
    __shared__ float Bs[2][TK][68];
    __shared__ float smu[TM], srs[TM];
    int tid = threadIdx.x;
    int tx = tid & 15, ty = tid >> 4;
    int m0 = blockIdx.x * TM, n0 = blockIdx.y * 64;
    int kbeg = blockIdx.z * kLen;
    int nk = kLen / TK;
    int ra = tid >> 2, qa = tid & 3;
    int rb = tid >> 4, qb = tid & 15;
    bool aload = (TM == 64) || (tid < TM * 4);

    if (zeroU && blockIdx.y == 0 && blockIdx.z == 0) {
        float4 z4 = make_float4(0.f, 0.f, 0.f, 0.f);
#pragma unroll
        for (int s = 0; s < TM / 4; s++)
            *(float4*)(zeroU + (size_t)m0 * 256 + s * 1024 + tid * 4) = z4;
        if (blockIdx.x == 0 && tid < 128)
            *(float4*)(zeroRS + tid * 4) = z4;
    }

    const float* Aptr = A + (size_t)(m0 + (aload ? ra : 0)) * K + kbeg + 4 * qa;
    const float* BptrT = B + (size_t)(n0 + ra) * K + kbeg + 4 * qa;
    const float* BptrN = B + (size_t)(kbeg + rb) * N + n0 + 4 * qb;

    float s1 = 0.f, s2 = 0.f;
    u64 acc[RM][2];
#pragma unroll
    for (int i = 0; i < RM; i++) { acc[i][0] = 0ull; acc[i][1] = 0ull; }

    float4 va = make_float4(0, 0, 0, 0);
    if (aload) va = *(const float4*)Aptr;
    float4 vb = bTrans ? *(const float4*)BptrT : *(const float4*)BptrN;
    if (aload) {
        As[0][4 * qa + 0][ra] = va.x; As[0][4 * qa + 1][ra] = va.y;
        As[0][4 * qa + 2][ra] = va.z; As[0][4 * qa + 3][ra] = va.w;
    }
    if (DO_LN) {
        s1 += va.x + va.y + va.z + va.w;
        s2 += va.x * va.x + va.y * va.y + va.z * va.z + va.w * va.w;
    }
    if (bTrans) {
        Bs[0][4 * qa + 0][ra] = vb.x; Bs[0][4 * qa + 1][ra] = vb.y;
        Bs[0][4 * qa + 2][ra] = vb.z; Bs[0][4 * qa + 3][ra] = vb.w;
    } else {
        *(float4*)&Bs[0][rb][4 * qb] = vb;
    }
    __syncthreads();

    for (int t = 0; t < nk; t++) {
        int cur = t & 1;
        bool has = (t + 1 < nk);
        if (has) {
            if (aload) va = *(const float4*)(Aptr + (t + 1) * TK);
            vb = bTrans ? *(const float4*)(BptrT + (t + 1) * TK)
                        : *(const float4*)(BptrN + (size_t)(t + 1) * TK * N);
        }
#pragma unroll
        for (int kk = 0; kk < TK; kk++) {
            float4 b4 = *(const float4*)&Bs[cur][kk][tx * 4];
            u64 b0 = pk2(b4.x, b4.y), b1p = pk2(b4.z, b4.w);
            float am[RM];
#pragma unroll
            for (int i = 0; i < RM; i++) am[i] = As[cur][kk][ty * RM + i];
#pragma unroll
            for (int i = 0; i < RM; i++) {
                u64 a2 = pk2(am[i], am[i]);
                acc[i][0] = fma2_(a2, b0, acc[i][0]);
                acc[i][1] = fma2_(a2, b1p, acc[i][1]);
            }
        }
        if (has) {
            int nb = cur ^ 1;
            if (aload) {
                As[nb][4 * qa + 0][ra] = va.x; As[nb][4 * qa + 1][ra] = va.y;
                As[nb][4 * qa + 2][ra] = va.z; As[nb][4 * qa + 3][ra] = va.w;
            }
            if (DO_LN) {
                s1 += va.x + va.y + va.z + va.w;
                s2 += va.x * va.x + va.y * va.y + va.z * va.z + va.w * va.w;
            }
            if (bTrans) {
                Bs[nb][4 * qa + 0][ra] = vb.x; Bs[nb][4 * qa + 1][ra] = vb.y;
                Bs[nb][4 * qa + 2][ra] = vb.z; Bs[nb][4 * qa + 3][ra] = vb.w;
            } else {
                *(float4*)&Bs[nb][rb][4 * qb] = vb;
            }
            __syncthreads();
        }
    }

    if (DO_LN) {
        s1 += __shfl_xor_sync(~0u, s1, 1); s2 += __shfl_xor_sync(~0u, s2, 1);
        s1 += __shfl_xor_sync(~0u, s1, 2); s2 += __shfl_xor_sync(~0u, s2, 2);
        if (aload && (tid & 3) == 0) {
            float mu = s1 * (1.f / 256.f);
            float var = fmaf(-mu, mu, s2 * (1.f / 256.f));
            smu[ra] = mu;
            srs[ra] = rsqrtf(var + 1e-5f);
        }
        __syncthreads();
    }

#pragma unroll
    for (int i = 0; i < RM; i++) {
        int m = m0 + ty * RM + i;
        float c[4];
        upk2(acc[i][0], c[0], c[1]);
        upk2(acc[i][1], c[2], c[3]);
        if (DO_LN) {
            float mu = smu[ty * RM + i], rstd = srs[ty * RM + i];
#pragma unroll
            for (int j = 0; j < 4; j++) {
                int n = n0 + tx * 4 + j;
                float v = c[j];
                if (n < lnCols) v = rstd * (v - mu * c1[n]);
                v += c2[n];
                if (relu) v = fmaxf(v, 0.f);
                if (C2 && n >= splitN) C2[(size_t)m * ldc2 + (n - splitN)] = v;
                else C[(size_t)m * ldc + n] = v;
            }
        } else {
            float rsf = rowden ? __fdividef(1.f, rowden[m]) : 1.f;
#pragma unroll
            for (int j = 0; j < 4; j++) {
                int n = n0 + tx * 4 + j;
                float v = c[j];
                if (rowden) v *= rsf;
                if (bias && blockIdx.z == 0) v += bias[n];
                if (relu) v = fmaxf(v, 0.f);
                if (atomicOut) atomicAdd(&C[(size_t)m * ldc + n], v);
                else C[(size_t)m * ldc + n] = v;
            }
        }
    }
}

// ---------------- merged precompute builder ----------------
__global__ void __launch_bounds__(256) build_misc_k(
    const float* __restrict__ Wqk, const float* __restrict__ gs,
    const float* __restrict__ bs, const float* __restrict__ whh,
    const float* __restrict__ bhh,
    const float* __restrict__ W1, const float* __restrict__ gm,
    const float* __restrict__ bm, const float* __restrict__ b1,
    float* __restrict__ Bcat, float* __restrict__ c1cat, float* __restrict__ c2cat,
    float* __restrict__ W1g, float* __restrict__ c1m, float* __restrict__ c2m)
{
    int x = blockIdx.x;
    int tid = threadIdx.x;
    if (x < 16) {
        __shared__ float r1[16][17], r2[16][17];
        int nn = tid & 15, kg = tid >> 4;
        int n = 16 * x + nn;
        float lc1 = 0.f, lc2 = 0.f;
#pragma unroll
        for (int r = 0; r < 16; r++) {
            int k = kg * 16 + r;
            float w = Wqk[(size_t)k * 256 + n];
            float gw = gs[k] * w;
            Bcat[(size_t)k * 1024 + n] = gw;
            lc1 += gw;
            lc2 += bs[k] * w;
        }
        r1[kg][nn] = lc1; r2[kg][nn] = lc2;
        __syncthreads();
        if (kg == 0) {
            float a = 0.f, b = 0.f;
#pragma unroll
            for (int i = 0; i < 16; i++) { a += r1[i][nn]; b += r2[i][nn]; }
            c1cat[n] = a; c2cat[n] = b;
        }
    } else if (x < 208) {
        __shared__ float tile[32][33];
        int t = x - 16;
        int n0 = (t % 24) * 32, k0 = (t / 24) * 32;
        int tx = tid & 31, ty = tid >> 5;
#pragma unroll
        for (int i = 0; i < 4; i++)
            tile[ty + 8 * i][tx] = whh[(size_t)(n0 + ty + 8 * i) * 256 + k0 + tx];
        __syncthreads();
#pragma unroll
        for (int i = 0; i < 4; i++)
            Bcat[(size_t)(k0 + ty + 8 * i) * 1024 + 256 + n0 + tx] = tile[tx][ty + 8 * i];
    } else if (x < 211) {
        int i = (x - 208) * 256 + tid;
        if (i < 768) c2cat[256 + i] = bhh[i];
    } else {
        int w = tid >> 5, lane = tid & 31;
        int row = (x - 211) * 8 + w;
        float lc1 = 0.f, lc2 = 0.f;
#pragma unroll
        for (int j = 0; j < 8; j++) {
            int col = lane + 32 * j;
            float v = W1[(size_t)row * 256 + col];
            float sc = gm[col] * v;
            W1g[(size_t)row * 256 + col] = sc;
            lc1 += sc;
            lc2 += bm[col] * v;
        }
#pragma unroll
        for (int o = 16; o; o >>= 1) {
            lc1 += __shfl_xor_sync(~0u, lc1, o);
            lc2 += __shfl_xor_sync(~0u, lc2, o);
        }
        if (lane == 0) { c1m[row] = lc1; c2m[row] = lc2 + b1[row]; }
    }
}

// ---------------- fused attention pass (round-12 exact: fp16 LN(features), 4-phase smem) ----------------
__global__ void __launch_bounds__(256, 3) attn_fused_k(
    const __half* __restrict__ flnh, const float* __restrict__ qk,
    float* __restrict__ attn_out, float* __restrict__ U, float* __restrict__ rowsum)
{
    __shared__ float fs[32][264];
    __shared__ float ds[32][9];
    __shared__ float as_[8][33];
    int tid = threadIdx.x, lane = tid & 31, w = tid >> 5;
    int b = blockIdx.y;
    int n0 = blockIdx.x * 128;
    int sg = w & 1, rg = w >> 1;

    u64 qkr2[4][4];
#pragma unroll
    for (int i = 0; i < 4; i++) {
        const float* qp = qk + ((size_t)(b * 8 + 4 * sg + i) << 8) + lane;
#pragma unroll
        for (int jj = 0; jj < 4; jj++)
            qkr2[i][jj] = pk2(qp[64 * jj], qp[64 * jj + 32]);
    }

    u64 u2[4][4];
#pragma unroll
    for (int i = 0; i < 4; i++)
#pragma unroll
        for (int jj = 0; jj < 4; jj++) u2[i][jj] = 0ull;
    float rs_acc[8];
#pragma unroll
    for (int i = 0; i < 8; i++) rs_acc[i] = 0.f;

    for (int t = 0; t < 4; t++) {
        // ---- P1: fp16 -> fp32 smem fill (coalesced, no LN math) ----
        const __half* fp = flnh + ((size_t)b * kN + n0 + t * 32 + 4 * w) * 256 + 4 * lane;
#pragma unroll
        for (int rr = 0; rr < 4; rr++) {
            uint2 ha = *(const uint2*)(fp + (size_t)rr * 256);
            uint2 hb = *(const uint2*)(fp + (size_t)rr * 256 + 128);
            __half2 h0 = *(__half2*)&ha.x, h1 = *(__half2*)&ha.y;
            __half2 h2 = *(__half2*)&hb.x, h3 = *(__half2*)&hb.y;
            float2 f0 = __half22float2(h0), f1 = __half22float2(h1);
            float2 f2c = __half22float2(h2), f3 = __half22float2(h3);
            float4 va = make_float4(f0.x, f0.y, f1.x, f1.y);
            float4 vb = make_float4(f2c.x, f2c.y, f3.x, f3.y);
            *(float4*)&fs[4 * w + rr][4 * lane] = va;
            *(float4*)&fs[4 * w + rr][128 + 4 * lane] = vb;
        }
        __syncthreads();
        // ---- P2: logits (strided LDS.32, merged shuffle tree) ----
#pragma unroll
        for (int rr = 0; rr < 8; rr++) {
            int row = 8 * rg + rr;
            u64 f2[4];
#pragma unroll
            for (int jj = 0; jj < 4; jj++)
                f2[jj] = pk2(fs[row][lane + 64 * jj], fs[row][lane + 64 * jj + 32]);
            float d[4];
#pragma unroll
            for (int i = 0; i < 4; i++) {
                u64 d2 = 0ull;
#pragma unroll
                for (int jj = 0; jj < 4; jj++) d2 = fma2_(qkr2[i][jj], f2[jj], d2);
                float lo, hi; upk2(d2, lo, hi);
                d[i] = lo + hi;
            }
            d[0] += __shfl_xor_sync(~0u, d[0], 1);
            d[1] += __shfl_xor_sync(~0u, d[1], 1);
            float m01 = (lane & 1) ? d[1] : d[0];
            d[2] += __shfl_xor_sync(~0u, d[2], 1);
            d[3] += __shfl_xor_sync(~0u, d[3], 1);
            float m23 = (lane & 1) ? d[3] : d[2];
            m01 += __shfl_xor_sync(~0u, m01, 2);
            m23 += __shfl_xor_sync(~0u, m23, 2);
            float mm = (lane & 2) ? m23 : m01;
            mm += __shfl_xor_sync(~0u, mm, 4);
            mm += __shfl_xor_sync(~0u, mm, 8);
            mm += __shfl_xor_sync(~0u, mm, 16);
            if (lane < 4) ds[row][4 * sg + lane] = mm;
        }
        __syncthreads();
        // ---- P3: softmax over slots (warp 0) ----
        if (w == 0) {
            float dd[8];
#pragma unroll
            for (int i = 0; i < 8; i++) dd[i] = ds[lane][i];
            float mx = dd[0];
#pragma unroll
            for (int i = 1; i < 8; i++) mx = fmaxf(mx, dd[i]);
            float e[8], sum = 0.f;
#pragma unroll
            for (int i = 0; i < 8; i++) { e[i] = __expf(0.0625f * (dd[i] - mx)); sum += e[i]; }
            float inv = __fdividef(1.f, sum);
#pragma unroll
            for (int i = 0; i < 8; i++) {
                float a = fmaf(e[i], inv, 1e-8f);
                rs_acc[i] += a;
                as_[i][lane] = a;
                attn_out[(size_t)(b * 8 + i) * 4096 + n0 + t * 32 + lane] = a;
            }
        }
        __syncthreads();
        // ---- P4: U accumulate ----
#pragma unroll
        for (int rr = 0; rr < 8; rr++) {
            int row = 8 * rg + rr;
            u64 f2[4];
#pragma unroll
            for (int jj = 0; jj < 4; jj++)
                f2[jj] = pk2(fs[row][lane + 64 * jj], fs[row][lane + 64 * jj + 32]);
#pragma unroll
            for (int i = 0; i < 4; i++) {
                float a = as_[4 * sg + i][row];
                u64 a2 = pk2(a, a);
#pragma unroll
                for (int jj = 0; jj < 4; jj++) u2[i][jj] = fma2_(a2, f2[jj], u2[i][jj]);
            }
        }
        __syncthreads();
    }

    // ---- block U reduction ----
    float* fsU = &fs[0][0];
#pragma unroll
    for (int i = 0; i < 8; i++) fsU[i * 264 + tid] = 0.f;
    __syncthreads();
#pragma unroll
    for (int i = 0; i < 4; i++)
#pragma unroll
        for (int jj = 0; jj < 4; jj++) {
            float lo, hi; upk2(u2[i][jj], lo, hi);
            atomicAdd(&fsU[(4 * sg + i) * 264 + lane + 64 * jj], lo);
            atomicAdd(&fsU[(4 * sg + i) * 264 + lane + 64 * jj + 32], hi);
        }
    __syncthreads();
#pragma unroll
    for (int i = 0; i < 8; i++)
        atomicAdd(&U[((size_t)(b * 8 + i) << 8) + tid], fsU[i * 264 + tid]);
    if (w == 0) {
#pragma unroll
        for (int i = 0; i < 8; i++) {
            float v = rs_acc[i];
#pragma unroll
            for (int o = 16; o; o >>= 1) v += __shfl_xor_sync(~0u, v, o);
            if (lane == 0) atomicAdd(&rowsum[b * 8 + i], v);
        }
    }
}

// ---------------- fused gi-GEMM (3 gates) + GRU, TM=32 ----------------
__global__ void __launch_bounds__(256) gru_gemm_k(
    const float* __restrict__ Uin, const float* __restrict__ Wvih,
    const float* __restrict__ rowsum, const float* __restrict__ b_ih,
    const float* __restrict__ gh, float* __restrict__ S0, float* __restrict__ S1)
{
    constexpr int TK = 16;
    __shared__ float As[2][TK][36];
    __shared__ float Bs[2][TK][208];
    int tid = threadIdx.x;
    int tx = tid & 15, ty = tid >> 4;
    int m0 = blockIdx.x * 32, c0 = blockIdx.y * 64;
    int ra = tid >> 2, qa = tid & 3;
    bool aload = tid < 128;

    const float* Aptr = Uin + (size_t)(m0 + (ra & 31)) * 256 + 4 * qa;

    u64 acc[3][2][2];
#pragma unroll
    for (int g = 0; g < 3; g++)
#pragma unroll
        for (int i = 0; i < 2; i++) { acc[g][i][0] = 0ull; acc[g][i][1] = 0ull; }

    float4 va = aload ? *(const float4*)Aptr : make_float4(0, 0, 0, 0);
    float4 vb[3];
#pragma unroll
    for (int g = 0; g < 3; g++)
        vb[g] = *(const float4*)(Wvih + (size_t)(g * 256 + c0 + ra) * 256 + 4 * qa);
    if (aload) {
        As[0][4 * qa + 0][ra] = va.x; As[0][4 * qa + 1][ra] = va.y;
        As[0][4 * qa + 2][ra] = va.z; As[0][4 * qa + 3][ra] = va.w;
    }
#pragma unroll
    for (int g = 0; g < 3; g++) {
        Bs[0][4 * qa + 0][g * 64 + ra] = vb[g].x;
        Bs[0][4 * qa + 1][g * 64 + ra] = vb[g].y;
        Bs[0][4 * qa + 2][g * 64 + ra] = vb[g].z;
        Bs[0][4 * qa + 3][g * 64 + ra] = vb[g].w;
    }
    __syncthreads();

    for (int t = 0; t < 16; t++) {
        int cur = t & 1;
        bool has = (t + 1 < 16);
        if (has) {
            if (aload) va = *(const float4*)(Aptr + (t + 1) * TK);
#pragma unroll
            for (int g = 0; g < 3; g++)
                vb[g] = *(const float4*)(Wvih + (size_t)(g * 256 + c0 + ra) * 256
                                         + (t + 1) * TK + 4 * qa);
        }
#pragma unroll
        for (int kk = 0; kk < TK; kk++) {
            float2 a2f = *(const float2*)&As[cur][kk][ty * 2];
            float am[2] = {a2f.x, a2f.y};
#pragma unroll
            for (int g = 0; g < 3; g++) {
                float4 b4 = *(const float4*)&Bs[cur][kk][g * 64 + tx * 4];
                u64 b0 = pk2(b4.x, b4.y), b1p = pk2(b4.z, b4.w);
#pragma unroll
                for (int i = 0; i < 2; i++) {
                    u64 a2 = pk2(am[i], am[i]);
                    acc[g][i][0] = fma2_(a2, b0, acc[g][i][0]);
                    acc[g][i][1] = fma2_(a2, b1p, acc[g][i][1]);
                }
            }
        }
        if (has) {
            int nb = cur ^ 1;
            if (aload) {
                As[nb][4 * qa + 0][ra] = va.x; As[nb][4 * qa + 1][ra] = va.y;
                As[nb][4 * qa + 2][ra] = va.z; As[nb][4 * qa + 3][ra] = va.w;
            }
#pragma unroll
            for (int g = 0; g < 3; g++) {
                Bs[nb][4 * qa + 0][g * 64 + ra] = vb[g].x;
                Bs[nb][4 * qa + 1][g * 64 + ra] = vb[g].y;
                Bs[nb][4 * qa + 2][g * 64 + ra] = vb[g].z;
                Bs[nb][4 * qa + 3][g * 64 + ra] = vb[g].w;
            }
            __syncthreads();
        }
    }

#pragma unroll
    for (int i = 0; i < 2; i++) {
        int m = m0 + ty * 2 + i;
        float inv = __fdividef(1.f, rowsum[m]);
        float rg_[4], zg[4], ng[4];
        upk2(acc[0][i][0], rg_[0], rg_[1]); upk2(acc[0][i][1], rg_[2], rg_[3]);
        upk2(acc[1][i][0], zg[0], zg[1]);   upk2(acc[1][i][1], zg[2], zg[3]);
        upk2(acc[2][i][0], ng[0], ng[1]);   upk2(acc[2][i][1], ng[2], ng[3]);
#pragma unroll
        for (int j = 0; j < 4; j++) {
            int c = c0 + tx * 4 + j;
            float ir = fmaf(rg_[j], inv, b_ih[c]);
            float iz = fmaf(zg[j], inv, b_ih[256 + c]);
            float in_ = fmaf(ng[j], inv, b_ih[512 + c]);
            size_t gb = (size_t)m * 768 + c;
            float hr = gh[gb], hz = gh[gb + 256], hn = gh[gb + 512];
            float r = 1.f / (1.f + __expf(-(ir + hr)));
            float z = 1.f / (1.f + __expf(-(iz + hz)));
            float nv = tanhf(fmaf(r, hn, in_));
            float h = S1[(size_t)m * 256 + c];
            float v = fmaf(z, h - nv, nv);
            S0[(size_t)m * 256 + c] = v;
            S1[(size_t)m * 256 + c] = v;
        }
    }
}

// ---------------- fused MLP, TM=64 ----------------
__global__ void __launch_bounds__(256) mlp_k(
    const float* __restrict__ S0, const float* __restrict__ W1g,
    const float* __restrict__ c1, const float* __restrict__ c2,
    const float* __restrict__ W2, const float* __restrict__ b2,
    float* __restrict__ S1)
{
    constexpr int TK = 16;
    __shared__ __align__(16) float sbuf[4352];
    __shared__ float hs[64][68];
    __shared__ float smu[64], srs[64];
#define AS_(b,k,i) sbuf[(b) * 1088 + (k) * 68 + (i)]
#define BS_(b,k,i) sbuf[2176 + (b) * 1088 + (k) * 68 + (i)]
#define W2S_(k,o)  sbuf[(k) * 68 + (o)]
    int tid = threadIdx.x;
    int tx = tid & 15, ty = tid >> 4;
    int m0 = blockIdx.x * 64, h0 = blockIdx.y * 64;
    int ra = tid >> 2, qa = tid & 3;

    const float* Aptr = S0 + (size_t)(m0 + ra) * 256 + 4 * qa;
    const float* Bptr = W1g + (size_t)(h0 + ra) * 256 + 4 * qa;

    float s1 = 0.f, s2 = 0.f;
    u64 acc[4][2];
#pragma unroll
    for (int i = 0; i < 4; i++) { acc[i][0] = 0ull; acc[i][1] = 0ull; }

    float4 va = *(const float4*)Aptr;
    float4 vb = *(const float4*)Bptr;
    AS_(0, 4 * qa + 0, ra) = va.x; AS_(0, 4 * qa + 1, ra) = va.y;
    AS_(0, 4 * qa + 2, ra) = va.z; AS_(0, 4 * qa + 3, ra) = va.w;
    s1 += va.x + va.y + va.z + va.w;
    s2 += va.x * va.x + va.y * va.y + va.z * va.z + va.w * va.w;
    BS_(0, 4 * qa + 0, ra) = vb.x; BS_(0, 4 * qa + 1, ra) = vb.y;
    BS_(0, 4 * qa + 2, ra) = vb.z; BS_(0, 4 * qa + 3, ra) = vb.w;
    __syncthreads();

    for (int t = 0; t < 16; t++) {
        int cur = t & 1;
        bool has = (t + 1 < 16);
        if (has) {
            va = *(const float4*)(Aptr + (t + 1) * TK);
            vb = *(const float4*)(Bptr + (t + 1) * TK);
        }
#pragma unroll
        for (int kk = 0; kk < TK; kk++) {
            float4 a4 = *(const float4*)&AS_(cur, kk, ty * 4);
            float4 b4 = *(const float4*)&BS_(cur, kk, tx * 4);
            u64 b0 = pk2(b4.x, b4.y), b1p = pk2(b4.z, b4.w);
            float am[4] = {a4.x, a4.y, a4.z, a4.w};
#pragma unroll
            for (int i = 0; i < 4; i++) {
                u64 a2 = pk2(am[i], am[i]);
                acc[i][0] = fma2_(a2, b0, acc[i][0]);
                acc[i][1] = fma2_(a2, b1p, acc[i][1]);
            }
        }
        if (has) {
            int nb = cur ^ 1;
            AS_(nb, 4 * qa + 0, ra) = va.x; AS_(nb, 4 * qa + 1, ra) = va.y;
            AS_(nb, 4 * qa + 2, ra) = va.z; AS_(nb, 4 * qa + 3, ra) = va.w;
            s1 += va.x + va.y + va.z + va.w;
            s2 += va.x * va.x + va.y * va.y + va.z * va.z + va.w * va.w;
            BS_(nb, 4 * qa + 0, ra) = vb.x; BS_(nb, 4 * qa + 1, ra) = vb.y;
            BS_(nb, 4 * qa + 2, ra) = vb.z; BS_(nb, 4 * qa + 3, ra) = vb.w;
            __syncthreads();
        }
    }

    s1 += __shfl_xor_sync(~0u, s1, 1); s2 += __shfl_xor_sync(~0u, s2, 1);
    s1 += __shfl_xor_sync(~0u, s1, 2); s2 += __shfl_xor_sync(~0u, s2, 2);
    if ((tid & 3) == 0) {
        float mu = s1 * (1.f / 256.f);
        float var = fmaf(-mu, mu, s2 * (1.f / 256.f));
        smu[ra] = mu;
        srs[ra] = rsqrtf(var + 1e-5f);
    }
    __syncthreads();

#pragma unroll
    for (int i = 0; i < 4; i++) {
        float mu = smu[ty * 4 + i], rstd = srs[ty * 4 + i];
        float c[4];
        upk2(acc[i][0], c[0], c[1]);
        upk2(acc[i][1], c[2], c[3]);
#pragma unroll
        for (int j = 0; j < 4; j++) {
            int n = h0 + tx * 4 + j;
            float v = rstd * (c[j] - mu * c1[n]) + c2[n];
            hs[ty * 4 + i][tx * 4 + j] = fmaxf(v, 0.f);
        }
    }
    __syncthreads();

    for (int ot = 0; ot < 4; ot++) {
#pragma unroll
        for (int tq = 0; tq < 4; tq++) {
            float4 w4 = *(const float4*)(W2 + (size_t)(ot * 64 + ra) * 1024 + h0
                                         + 16 * qa + 4 * tq);
            W2S_(16 * qa + 4 * tq + 0, ra) = w4.x;
            W2S_(16 * qa + 4 * tq + 1, ra) = w4.y;
            W2S_(16 * qa + 4 * tq + 2, ra) = w4.z;
            W2S_(16 * qa + 4 * tq + 3, ra) = w4.w;
        }
        __syncthreads();

        u64 acc2[4][2];
#pragma unroll
        for (int i = 0; i < 4; i++) { acc2[i][0] = 0ull; acc2[i][1] = 0ull; }
#pragma unroll
        for (int k4 = 0; k4 < 64; k4 += 4) {
            float4 h4[4];
#pragma unroll
            for (int i = 0; i < 4; i++)
                h4[i] = *(const float4*)&hs[ty * 4 + i][k4];
#pragma unroll
            for (int u = 0; u < 4; u++) {
                float4 b4 = *(const float4*)&W2S_(k4 + u, tx * 4);
                u64 b0 = pk2(b4.x, b4.y), b1p = pk2(b4.z, b4.w);
                float hm[4] = {
                    u == 0 ? h4[0].x : u == 1 ? h4[0].y : u == 2 ? h4[0].z : h4[0].w,
                    u == 0 ? h4[1].x : u == 1 ? h4[1].y : u == 2 ? h4[1].z : h4[1].w,
                    u == 0 ? h4[2].x : u == 1 ? h4[2].y : u == 2 ? h4[2].z : h4[2].w,
                    u == 0 ? h4[3].x : u == 1 ? h4[3].y : u == 2 ? h4[3].z : h4[3].w};
#pragma unroll
                for (int i = 0; i < 4; i++) {
                    u64 a2 = pk2(hm[i], hm[i]);
                    acc2[i][0] = fma2_(a2, b0, acc2[i][0]);
                    acc2[i][1] = fma2_(a2, b1p, acc2[i][1]);
                }
            }
        }
#pragma unroll
        for (int i = 0; i < 4; i++) {
            int m = m0 + ty * 4 + i;
            float c[4];
            upk2(acc2[i][0], c[0], c[1]);
            upk2(acc2[i][1], c[2], c[3]);
#pragma unroll
            for (int j = 0; j < 4; j++) {
                int n = ot * 64 + tx * 4 + j;
                float v = c[j];
                if (blockIdx.y == 0) v += b2[n];
                atomicAdd(&S1[(size_t)m * 256 + n], v);
            }
        }
        __syncthreads();
    }
#undef AS_
#undef BS_
#undef W2S_
}

// ---------------- launcher ----------------
extern "C" void kernel_launch(void* const* d_in, const int* in_sizes, int n_in,
                              void* d_out, int out_size)
{
    const float* features   = (const float*)d_in[0];
    const float* slots_init = (const float*)d_in[1];
    const float* g_feat     = (const float*)d_in[2];
    const float* b_feat     = (const float*)d_in[3];
    const float* g_slots    = (const float*)d_in[4];
    const float* b_slots    = (const float*)d_in[5];
    const float* g_mlp      = (const float*)d_in[6];
    const float* b_mlp      = (const float*)d_in[7];
    const float* Wk         = (const float*)d_in[8];
    const float* Wv         = (const float*)d_in[9];
    const float* Wq         = (const float*)d_in[10];
    const float* w_ih       = (const float*)d_in[11];
    const float* w_hh       = (const float*)d_in[12];
    const float* b_ih       = (const float*)d_in[13];
    const float* b_hh       = (const float*)d_in[14];
    const float* W1         = (const float*)d_in[15];
    const float* b1         = (const float*)d_in[16];
    const float* W2         = (const float*)d_in[17];
    const float* b2         = (const float*)d_in[18];

    float* out       = (float*)d_out;
    float* out_slots = out;
    float* out_attn  = out + (size_t)64 * 8 * 256;

    float *S0, *S1, *qkbuf, *U, *rowsum, *gh;
    float *Wqk, *Bcat, *c1cat, *c2cat, *W1g, *c1m, *c2m, *Wvih;
    __half* flnh;
    cudaGetSymbolAddress((void**)&S0, g_S0);
    cudaGetSymbolAddress((void**)&S1, g_S1);
    cudaGetSymbolAddress((void**)&qkbuf, g_qkbuf);
    cudaGetSymbolAddress((void**)&U, g_Ubuf);
    cudaGetSymbolAddress((void**)&rowsum, g_rowsum);
    cudaGetSymbolAddress((void**)&gh, g_gh);
    cudaGetSymbolAddress((void**)&Wqk, g_Wqk);
    cudaGetSymbolAddress((void**)&Bcat, g_Bcat);
    cudaGetSymbolAddress((void**)&c1cat, g_c1cat);
    cudaGetSymbolAddress((void**)&c2cat, g_c2cat);
    cudaGetSymbolAddress((void**)&W1g, g_W1g);
    cudaGetSymbolAddress((void**)&c1m, g_c1m);
    cudaGetSymbolAddress((void**)&c2m, g_c2m);
    cudaGetSymbolAddress((void**)&Wvih, g_Wvih);
    cudaGetSymbolAddress((void**)&flnh, g_flnh);

    // mega precompute: gemm_tn + Wvih gemm + S1 copy hidden under ln_feat
    mega_pre_k<<<192 + 64 * 4096 / 8, 256>>>(
        features, g_feat, b_feat, flnh,
        Wq, Wk, Wqk, w_ih, Wv, Wvih, slots_init, S1);
    build_misc_k<<<339, 256>>>(Wqk, g_slots, b_slots, w_hh, b_hh,
                               W1, g_mlp, b_mlp, b1,
                               Bcat, c1cat, c2cat, W1g, c1m, c2m);

    for (int it = 0; it < kNITER; it++) {
        // [qk | gh] = LN(S1)@Wqk | S1@w_hh^T + b_hh; side job: zero U/rowsum
        gemm2_k<1, 32><<<dim3(16, 16), 256>>>(S1, Bcat, qkbuf, 256, gh, 768, 256,
                                              1024, 256, 256, 0,
                                              c1cat, c2cat, 256, nullptr, nullptr, 0, 0,
                                              U, rowsum);
        attn_fused_k<<<dim3(32, 64), 256>>>(flnh, qkbuf, out_attn, U, rowsum);
        gru_gemm_k<<<dim3(16, 4), 256>>>(U, Wvih, rowsum, b_ih, gh, S0, S1);
        mlp_k<<<dim3(8, 16), 256>>>(S0, W1g, c1m, c2m, W2, b2, S1);
    }
    cudaMemcpyAsync(out_slots, S1, (size_t)512 * 256 * 4,
                    cudaMemcpyDeviceToDevice, 0);
}